// round 13
// baseline (speedup 1.0000x reference)
#include <cuda_runtime.h>
#include <cuda_bf16.h>
#include <math_constants.h>

#define THREADS 512
#define D 4096
#define V4R (D / 4 / THREADS)   // 2 float4 per thread per row
#define EPR (V4R * 4)           // 8 elems per thread per row
#define NW (THREADS / 32)       // 16 warps
#define CANDCAP 64
#define SORTN 32

// Exact sparsemax threshold from <=32 candidates held in shared memory.
// Warp-collective (one warp). Bitonic sort desc + prefix + support test.
__device__ __forceinline__ float solve_tau(const float* __restrict__ cand, int cnt, int lane)
{
    const unsigned FULL = 0xFFFFFFFFu;
    if (cnt <= 16) {
        const int l4 = lane & 15;
        float v = (lane < cnt) ? cand[lane] : -CUDART_INF_F;
#pragma unroll
        for (int k = 2; k <= 16; k <<= 1) {
#pragma unroll
            for (int j = k >> 1; j > 0; j >>= 1) {
                float w = __shfl_xor_sync(FULL, v, j);
                bool lower   = ((l4 & j) == 0);
                bool descBlk = ((l4 & k) == 0);
                v = (lower == descBlk) ? fmaxf(v, w) : fminf(v, w);
            }
        }
        float csum = v;
#pragma unroll
        for (int off = 1; off < 16; off <<= 1) {
            float u = __shfl_up_sync(FULL, csum, off, 16);
            if (l4 >= off) csum += u;
        }
        float r = (float)(l4 + 1);
        bool cond = (lane < cnt) && (1.0f + r * v > csum);
        unsigned msk = __ballot_sync(FULL, cond);        // only lanes 0..15 can set
        int kidx = 31 - __clz(msk);
        float csk = __shfl_sync(FULL, csum, kidx);
        return (csk - 1.0f) / (float)(kidx + 1);
    } else {
        float v = (lane < cnt) ? cand[lane] : -CUDART_INF_F;
#pragma unroll
        for (int k = 2; k <= 32; k <<= 1) {
#pragma unroll
            for (int j = k >> 1; j > 0; j >>= 1) {
                float w = __shfl_xor_sync(FULL, v, j);
                bool lower   = ((lane & j) == 0);
                bool descBlk = ((lane & k) == 0);
                v = (lower == descBlk) ? fmaxf(v, w) : fminf(v, w);
            }
        }
        float csum = v;
#pragma unroll
        for (int off = 1; off < 32; off <<= 1) {
            float u = __shfl_up_sync(FULL, csum, off);
            if (lane >= off) csum += u;
        }
        float r = (float)(lane + 1);
        bool cond = (lane < cnt) && (1.0f + r * v > csum);
        unsigned msk = __ballot_sync(FULL, cond);
        int kidx = 31 - __clz(msk);
        float csk = __shfl_sync(FULL, csum, kidx);
        return (csk - 1.0f) / (float)(kidx + 1);
    }
}

__global__ __launch_bounds__(THREADS, 4)
void sparsemax_kernel(const float* __restrict__ in, float* __restrict__ out)
{
    const long long rowA = 2LL * blockIdx.x;
    const float4* __restrict__ rinA = reinterpret_cast<const float4*>(in + rowA * D);
    const float4* __restrict__ rinB = reinterpret_cast<const float4*>(in + (rowA + 1) * D);
    float* __restrict__ routAf = out + rowA * D;
    float* __restrict__ routBf = out + (rowA + 1) * D;
    float4* __restrict__ routA = reinterpret_cast<float4*>(routAf);
    float4* __restrict__ routB = reinterpret_cast<float4*>(routBf);

    const int t    = threadIdx.x;
    const int lane = t & 31;
    const int wid  = t >> 5;
    const unsigned FULL = 0xFFFFFFFFu;

    __shared__ float redA[NW], redB[NW];
    __shared__ float fsA[NW], fkA[NW], fsB[NW], fkB[NW];   // fallback only
    __shared__ float candA[CANDCAP], candB[CANDCAP];
    __shared__ int   cidxA[CANDCAP], cidxB[CANDCAP];
    __shared__ int   s_cnt[2];
    __shared__ float s_tau[2];
    __shared__ int   s_done;

    if (t == 0) { s_cnt[0] = 0; s_cnt[1] = 0; }

    // ---- Load both rows: 4 independent LDG.128 in flight (MLP=4)
    float4 a0 = __ldcs(rinA + t);
    float4 a1 = __ldcs(rinA + t + THREADS);
    float4 b0 = __ldcs(rinB + t);
    float4 b1 = __ldcs(rinB + t + THREADS);

    float za[EPR] = {a0.x, a0.y, a0.z, a0.w, a1.x, a1.y, a1.z, a1.w};
    float zb[EPR] = {b0.x, b0.y, b0.z, b0.w, b1.x, b1.y, b1.z, b1.w};

    float tma = fmaxf(fmaxf(fmaxf(za[0], za[1]), fmaxf(za[2], za[3])),
                      fmaxf(fmaxf(za[4], za[5]), fmaxf(za[6], za[7])));
    float tmb = fmaxf(fmaxf(fmaxf(zb[0], zb[1]), fmaxf(zb[2], zb[3])),
                      fmaxf(fmaxf(zb[4], zb[5]), fmaxf(zb[6], zb[7])));

    // ---- Warp maxes (both rows interleaved; latencies shared)
    float ma = tma, mb = tmb;
#pragma unroll
    for (int off = 16; off >= 1; off >>= 1) {
        ma = fmaxf(ma, __shfl_xor_sync(FULL, ma, off));
        mb = fmaxf(mb, __shfl_xor_sync(FULL, mb, off));
    }
    if (lane == 0) { redA[wid] = ma; redB[wid] = mb; }
    __syncthreads();                        // B0

    // ---- Block maxes: lanes<16 load, 4-stage fold, broadcast
    float xa = (lane < NW) ? redA[lane] : -CUDART_INF_F;
    float xb = (lane < NW) ? redB[lane] : -CUDART_INF_F;
#pragma unroll
    for (int off = 8; off >= 1; off >>= 1) {
        xa = fmaxf(xa, __shfl_xor_sync(FULL, xa, off));
        xb = fmaxf(xb, __shfl_xor_sync(FULL, xb, off));
    }
    const float loA = __shfl_sync(FULL, xa, 0) - 1.0f;   // tauA in [loA, zmaxA)
    const float loB = __shfl_sync(FULL, xb, 0) - 1.0f;

    // ---- Compaction (values + global indices), ~0.3% of threads per row
    if (tma > loA) {
#pragma unroll
        for (int i = 0; i < EPR; ++i) {
            if (za[i] > loA) {
                int pos = atomicAdd(&s_cnt[0], 1);
                if (pos < CANDCAP) {
                    candA[pos] = za[i];
                    cidxA[pos] = 4 * (t + (i >> 2) * THREADS) + (i & 3);
                }
            }
        }
    }
    if (tmb > loB) {
#pragma unroll
        for (int i = 0; i < EPR; ++i) {
            if (zb[i] > loB) {
                int pos = atomicAdd(&s_cnt[1], 1);
                if (pos < CANDCAP) {
                    candB[pos] = zb[i];
                    cidxB[pos] = 4 * (t + (i >> 2) * THREADS) + (i & 3);
                }
            }
        }
    }
    __syncthreads();                        // B1
    const int cntA = s_cnt[0];
    const int cntB = s_cnt[1];

    if (cntA <= SORTN && cntB <= SORTN) {
        // ---- Uniform zero epilogue for BOTH rows (tau >= lo => non-candidates = 0)
        const float4 zero = make_float4(0.0f, 0.0f, 0.0f, 0.0f);
        __stcs(routA + t, zero);
        __stcs(routA + t + THREADS, zero);
        __stcs(routB + t, zero);
        __stcs(routB + t + THREADS, zero);

        // ---- Warp 0 solves row A, warp 1 solves row B — concurrently
        float tau = 0.0f;
        if (wid == 0)      tau = solve_tau(candA, cntA, lane);
        else if (wid == 1) tau = solve_tau(candB, cntB, lane);
        __syncthreads();                    // B2: zeros ordered before fixups

        // ---- Fixups: overwrite the <=cnt candidate slots with true values
        if (wid == 0 && lane < cntA)
            routAf[cidxA[lane]] = fmaxf(candA[lane] - tau, 0.0f);
        else if (wid == 1 && lane < cntB)
            routBf[cidxB[lane]] = fmaxf(candB[lane] - tau, 0.0f);
    } else {
        // ---- Fallback (arbitrary data): dual-row block-wide Newton
        if (t == 0) { s_tau[0] = loA; s_tau[1] = loB; }
        __syncthreads();
        float ta = s_tau[0], tb = s_tau[1];
        for (int it = 0; it < 48; ++it) {
            float sa = 0.0f, ka = 0.0f, sb = 0.0f, kb = 0.0f;
#pragma unroll
            for (int i = 0; i < EPR; ++i) {
                float da = za[i] - ta; if (da > 0.0f) { sa += da; ka += 1.0f; }
                float db = zb[i] - tb; if (db > 0.0f) { sb += db; kb += 1.0f; }
            }
#pragma unroll
            for (int off = 16; off >= 1; off >>= 1) {
                sa += __shfl_xor_sync(FULL, sa, off);
                ka += __shfl_xor_sync(FULL, ka, off);
                sb += __shfl_xor_sync(FULL, sb, off);
                kb += __shfl_xor_sync(FULL, kb, off);
            }
            if (lane == 0) { fsA[wid] = sa; fkA[wid] = ka; fsB[wid] = sb; fkB[wid] = kb; }
            __syncthreads();
            if (t == 0) {
                float SA = 0.0f, KA = 0.0f, SB = 0.0f, KB = 0.0f;
#pragma unroll
                for (int w = 0; w < NW; ++w) {
                    SA += fsA[w]; KA += fkA[w]; SB += fsB[w]; KB += fkB[w];
                }
                float dA = (SA - 1.0f) / KA;
                float dB = (SB - 1.0f) / KB;
                s_tau[0] = ta + dA;
                s_tau[1] = tb + dB;
                s_done = (dA < 1e-7f) && (dB < 1e-7f);
            }
            __syncthreads();
            ta = s_tau[0]; tb = s_tau[1];
            if (s_done) break;
        }
        float4 oa0, oa1, ob0, ob1;
        oa0.x = fmaxf(za[0] - ta, 0.0f); oa0.y = fmaxf(za[1] - ta, 0.0f);
        oa0.z = fmaxf(za[2] - ta, 0.0f); oa0.w = fmaxf(za[3] - ta, 0.0f);
        oa1.x = fmaxf(za[4] - ta, 0.0f); oa1.y = fmaxf(za[5] - ta, 0.0f);
        oa1.z = fmaxf(za[6] - ta, 0.0f); oa1.w = fmaxf(za[7] - ta, 0.0f);
        ob0.x = fmaxf(zb[0] - tb, 0.0f); ob0.y = fmaxf(zb[1] - tb, 0.0f);
        ob0.z = fmaxf(zb[2] - tb, 0.0f); ob0.w = fmaxf(zb[3] - tb, 0.0f);
        ob1.x = fmaxf(zb[4] - tb, 0.0f); ob1.y = fmaxf(zb[5] - tb, 0.0f);
        ob1.z = fmaxf(zb[6] - tb, 0.0f); ob1.w = fmaxf(zb[7] - tb, 0.0f);
        __stcs(routA + t, oa0);
        __stcs(routA + t + THREADS, oa1);
        __stcs(routB + t, ob0);
        __stcs(routB + t + THREADS, ob1);
    }
}

extern "C" void kernel_launch(void* const* d_in, const int* in_sizes, int n_in,
                              void* d_out, int out_size)
{
    const float* in  = (const float*)d_in[0];
    float*       out = (float*)d_out;
    const int n_rows = in_sizes[0] / D;   // 16384 (even)
    sparsemax_kernel<<<n_rows / 2, THREADS>>>(in, out);
}

// round 15
// speedup vs baseline: 1.0884x; 1.0884x over previous
#include <cuda_runtime.h>
#include <cuda_bf16.h>
#include <math_constants.h>

#define THREADS 256
#define D 4096
#define V4T (D / 4 / THREADS)   // 4 float4 per thread
#define EPT (V4T * 4)           // 16 floats per thread
#define NW (THREADS / 32)       // 8 warps
#define CANDCAP 64
#define SORTN 32

__global__ __launch_bounds__(THREADS, 8)
void sparsemax_kernel(const float* __restrict__ in, float* __restrict__ out)
{
    const long long row = blockIdx.x;
    const float4* __restrict__ rin   = reinterpret_cast<const float4*>(in + row * (long long)D);
    float*        __restrict__ routf = out + row * (long long)D;

    const int t    = threadIdx.x;
    const int lane = t & 31;
    const int wid  = t >> 5;
    const unsigned FULL = 0xFFFFFFFFu;

    __shared__ float red[NW];
    __shared__ float redb[NW];
    __shared__ float cand[CANDCAP];
    __shared__ int   cidx[CANDCAP];
    __shared__ int   s_cnt;
    __shared__ float s_tau;
    __shared__ int   s_done;

    if (t == 0) s_cnt = 0;

    // ---- Load 16 elements/thread (4x LDG.128 .cs), track thread max
    float z[EPT];
    float tm;
#pragma unroll
    for (int i = 0; i < V4T; ++i) {
        float4 v = __ldcs(rin + t + i * THREADS);
        z[4*i+0] = v.x; z[4*i+1] = v.y; z[4*i+2] = v.z; z[4*i+3] = v.w;
        float q = fmaxf(fmaxf(v.x, v.y), fmaxf(v.z, v.w));
        tm = (i == 0) ? q : fmaxf(tm, q);
    }

    // ---- Warp max -> smem
    float m = tm;
#pragma unroll
    for (int off = 16; off >= 1; off >>= 1)
        m = fmaxf(m, __shfl_xor_sync(FULL, m, off));
    if (lane == 0) red[wid] = m;
    __syncthreads();                       // B0: maxes + s_cnt=0 visible

    // ---- Block max: lanes<8 load red[], 3-stage fold, broadcast
    float zmax = (lane < NW) ? red[lane] : -CUDART_INF_F;
#pragma unroll
    for (int off = 4; off >= 1; off >>= 1)
        zmax = fmaxf(zmax, __shfl_xor_sync(FULL, zmax, off));
    zmax = __shfl_sync(FULL, zmax, 0);
    const float lo = zmax - 1.0f;          // tau in [lo, zmax): only z > lo matter

    // ---- Compaction (values + global indices); ~0.3% of threads enter
    if (tm > lo) {
#pragma unroll
        for (int i = 0; i < EPT; ++i) {
            if (z[i] > lo) {
                int pos = atomicAdd(&s_cnt, 1);
                if (pos < CANDCAP) {
                    cand[pos] = z[i];
                    cidx[pos] = 4 * (t + (i >> 2) * THREADS) + (i & 3);
                }
            }
        }
    }
    __syncthreads();                       // B1: candidates visible
    const int cnt = s_cnt;

    if (cnt <= SORTN) {
        // ---- Output is already all-zeros (memset before this kernel in-stream).
        // Only warp 0 solves + scatters the <=cnt true values; others exit now.
        if (wid != 0) return;

        float tau;
        if (cnt <= 16) {
            // 16-lane bitonic (10 sort + 4 scan stages)
            const int l4 = lane & 15;
            float v = (lane < cnt) ? cand[lane] : -CUDART_INF_F;
#pragma unroll
            for (int k = 2; k <= 16; k <<= 1) {
#pragma unroll
                for (int j = k >> 1; j > 0; j >>= 1) {
                    float w = __shfl_xor_sync(FULL, v, j);
                    bool lower   = ((l4 & j) == 0);
                    bool descBlk = ((l4 & k) == 0);
                    v = (lower == descBlk) ? fmaxf(v, w) : fminf(v, w);
                }
            }
            float csum = v;
#pragma unroll
            for (int off = 1; off < 16; off <<= 1) {
                float u = __shfl_up_sync(FULL, csum, off, 16);
                if (l4 >= off) csum += u;
            }
            float r = (float)(l4 + 1);
            bool cond = (lane < cnt) && (1.0f + r * v > csum);
            unsigned msk = __ballot_sync(FULL, cond);    // lanes 0..15 only
            int kidx = 31 - __clz(msk);
            float csk = __shfl_sync(FULL, csum, kidx);
            tau = (csk - 1.0f) / (float)(kidx + 1);
        } else {
            // 32-lane bitonic (rare)
            float v = (lane < cnt) ? cand[lane] : -CUDART_INF_F;
#pragma unroll
            for (int k = 2; k <= 32; k <<= 1) {
#pragma unroll
                for (int j = k >> 1; j > 0; j >>= 1) {
                    float w = __shfl_xor_sync(FULL, v, j);
                    bool lower   = ((lane & j) == 0);
                    bool descBlk = ((lane & k) == 0);
                    v = (lower == descBlk) ? fmaxf(v, w) : fminf(v, w);
                }
            }
            float csum = v;
#pragma unroll
            for (int off = 1; off < 32; off <<= 1) {
                float u = __shfl_up_sync(FULL, csum, off);
                if (lane >= off) csum += u;
            }
            float r = (float)(lane + 1);
            bool cond = (lane < cnt) && (1.0f + r * v > csum);
            unsigned msk = __ballot_sync(FULL, cond);
            int kidx = 31 - __clz(msk);
            float csk = __shfl_sync(FULL, csum, kidx);
            tau = (csk - 1.0f) / (float)(kidx + 1);
        }

        // ---- Scatter fixups: only candidate slots differ from zero
        if (lane < cnt)
            routf[cidx[lane]] = fmaxf(cand[lane] - tau, 0.0f);
    } else {
        // ---- Fallback (arbitrary data): block-wide Newton + full epilogue
        // (overwrites the memset zeros everywhere; tau >= lo guaranteed)
        if (t == 0) s_tau = lo;
        __syncthreads();
        float tloc = s_tau;
        for (int it = 0; it < 48; ++it) {
            float s = 0.0f, k = 0.0f;
#pragma unroll
            for (int i = 0; i < EPT; ++i) {
                float d = z[i] - tloc;
                if (d > 0.0f) { s += d; k += 1.0f; }
            }
#pragma unroll
            for (int off = 16; off >= 1; off >>= 1) {
                s += __shfl_xor_sync(FULL, s, off);
                k += __shfl_xor_sync(FULL, k, off);
            }
            if (lane == 0) { red[wid] = s; redb[wid] = k; }
            __syncthreads();
            if (t == 0) {
                float S = 0.0f, K = 0.0f;
#pragma unroll
                for (int w = 0; w < NW; ++w) { S += red[w]; K += redb[w]; }
                float delta = (S - 1.0f) / K;
                s_tau  = tloc + delta;
                s_done = (delta < 1e-7f);
            }
            __syncthreads();
            tloc = s_tau;
            if (s_done) break;
        }
        const float tau = s_tau;
        float4* rout = reinterpret_cast<float4*>(routf);
#pragma unroll
        for (int i = 0; i < V4T; ++i) {
            float4 o;
            o.x = fmaxf(z[4*i+0] - tau, 0.0f);
            o.y = fmaxf(z[4*i+1] - tau, 0.0f);
            o.z = fmaxf(z[4*i+2] - tau, 0.0f);
            o.w = fmaxf(z[4*i+3] - tau, 0.0f);
            __stcs(rout + t + i * THREADS, o);
        }
    }
}

extern "C" void kernel_launch(void* const* d_in, const int* in_sizes, int n_in,
                              void* d_out, int out_size)
{
    const float* in  = (const float*)d_in[0];
    float*       out = (float*)d_out;
    const int n_rows = in_sizes[0] / D;   // 16384

    // Pure write stream: HW-optimized memset zeroes the output (graph-capturable,
    // no allocation). Stream-ordered before the kernel's scatter fixups.
    cudaMemsetAsync(d_out, 0, (size_t)out_size * sizeof(float), 0);
    sparsemax_kernel<<<n_rows, THREADS>>>(in, out);
}

// round 17
// speedup vs baseline: 1.3619x; 1.2512x over previous
#include <cuda_runtime.h>
#include <cuda_bf16.h>
#include <math_constants.h>

#define WORKERS 256              // 8 worker warps
#define THREADS 288              // + 1 solver warp (wid 8)
#define D 4096
#define V4T (D / 4 / WORKERS)    // 4 float4 per worker thread
#define EPT (V4T * 4)            // 16 floats per worker thread
#define NW 8                     // worker warps
#define SOLVER 8                 // solver warp id
#define CANDCAP 64
#define SORTN 32
#define NCTAS 2048

// Exact sparsemax threshold from <=32 candidates (warp-collective, any warp).
__device__ __forceinline__ float solve_tau(const float* __restrict__ cand, int cnt, int lane)
{
    const unsigned FULL = 0xFFFFFFFFu;
    if (cnt <= 16) {
        const int l4 = lane & 15;
        float v = (lane < cnt) ? cand[lane] : -CUDART_INF_F;
#pragma unroll
        for (int k = 2; k <= 16; k <<= 1) {
#pragma unroll
            for (int j = k >> 1; j > 0; j >>= 1) {
                float w = __shfl_xor_sync(FULL, v, j);
                bool lower   = ((l4 & j) == 0);
                bool descBlk = ((l4 & k) == 0);
                v = (lower == descBlk) ? fmaxf(v, w) : fminf(v, w);
            }
        }
        float csum = v;
#pragma unroll
        for (int off = 1; off < 16; off <<= 1) {
            float u = __shfl_up_sync(FULL, csum, off, 16);
            if (l4 >= off) csum += u;
        }
        float r = (float)(l4 + 1);
        bool cond = (lane < cnt) && (1.0f + r * v > csum);
        unsigned msk = __ballot_sync(FULL, cond);
        int kidx = 31 - __clz(msk);
        float csk = __shfl_sync(FULL, csum, kidx);
        return (csk - 1.0f) / (float)(kidx + 1);
    } else {
        float v = (lane < cnt) ? cand[lane] : -CUDART_INF_F;
#pragma unroll
        for (int k = 2; k <= 32; k <<= 1) {
#pragma unroll
            for (int j = k >> 1; j > 0; j >>= 1) {
                float w = __shfl_xor_sync(FULL, v, j);
                bool lower   = ((lane & j) == 0);
                bool descBlk = ((lane & k) == 0);
                v = (lower == descBlk) ? fmaxf(v, w) : fminf(v, w);
            }
        }
        float csum = v;
#pragma unroll
        for (int off = 1; off < 32; off <<= 1) {
            float u = __shfl_up_sync(FULL, csum, off);
            if (lane >= off) csum += u;
        }
        float r = (float)(lane + 1);
        bool cond = (lane < cnt) && (1.0f + r * v > csum);
        unsigned msk = __ballot_sync(FULL, cond);
        int kidx = 31 - __clz(msk);
        float csk = __shfl_sync(FULL, csum, kidx);
        return (csk - 1.0f) / (float)(kidx + 1);
    }
}

__global__ __launch_bounds__(THREADS, 6)
void sparsemax_kernel(const float* __restrict__ in, float* __restrict__ out, int n_rows)
{
    __shared__ float red[NW];
    __shared__ float cand[2][CANDCAP];
    __shared__ int   cidx[2][CANDCAP];
    __shared__ int   s_cnt[2];
    __shared__ float fred[NW + 1], fredb[NW + 1];   // fallback only
    __shared__ float s_tau;
    __shared__ int   s_done;

    const int t    = threadIdx.x;
    const int lane = t & 31;
    const int wid  = t >> 5;
    const bool isW = (wid < NW);            // worker warps 0..7, solver = warp 8
    const unsigned FULL = 0xFFFFFFFFu;
    const int G = gridDim.x;

    if (t == 0) { s_cnt[0] = 0; s_cnt[1] = 0; }

    int iter = 0;
    for (long long row = blockIdx.x; row < n_rows; row += G, ++iter) {
        const int p = iter & 1;
        const float4* __restrict__ rin   = reinterpret_cast<const float4*>(in + row * (long long)D);
        float*        __restrict__ routf = out + row * (long long)D;

        // ---- Workers: load 16 elems (4x LDG.128 .cs), warp max
        float z[EPT];
        float tm = -CUDART_INF_F;
        if (isW) {
#pragma unroll
            for (int i = 0; i < V4T; ++i) {
                float4 v = __ldcs(rin + t + i * WORKERS);
                z[4*i+0] = v.x; z[4*i+1] = v.y; z[4*i+2] = v.z; z[4*i+3] = v.w;
                tm = fmaxf(tm, fmaxf(fmaxf(v.x, v.y), fmaxf(v.z, v.w)));
            }
            float m = tm;
#pragma unroll
            for (int off = 16; off >= 1; off >>= 1)
                m = fmaxf(m, __shfl_xor_sync(FULL, m, off));
            if (lane == 0) red[wid] = m;
        }
        __syncthreads();                    // B0(row)

        // reset OFF-parity counter for the next row; barrier-ordered against
        // the solver's read of s_cnt[p^1] (which happened before its B0 arrival)
        if (t == 0) s_cnt[p ^ 1] = 0;

        float lo = 0.0f;
        if (isW) {
            float zm = (lane < NW) ? red[lane] : -CUDART_INF_F;
#pragma unroll
            for (int off = 4; off >= 1; off >>= 1)
                zm = fmaxf(zm, __shfl_xor_sync(FULL, zm, off));
            lo = __shfl_sync(FULL, zm, 0) - 1.0f;   // tau in [lo, zmax)

            // ---- compaction (values + indices) into parity-p buffers
            if (tm > lo) {
#pragma unroll
                for (int i = 0; i < EPT; ++i) {
                    if (z[i] > lo) {
                        int pos = atomicAdd(&s_cnt[p], 1);
                        if (pos < CANDCAP) {
                            cand[p][pos] = z[i];
                            cidx[p][pos] = 4 * (t + (i >> 2) * WORKERS) + (i & 3);
                        }
                    }
                }
            }
        }
        __syncthreads();                    // B1(row)
        const int cnt = s_cnt[p];

        if (cnt <= SORTN) {
            if (isW) {
                // ---- zero-store every NON-candidate slot (z <= lo <= tau -> 0).
                // Candidate slots (z > lo) are skipped: solver writes them.
                // Complementary sets => every address written exactly once.
                float4* rout4 = reinterpret_cast<float4*>(routf);
                const float4 zero = make_float4(0.0f, 0.0f, 0.0f, 0.0f);
#pragma unroll
                for (int q = 0; q < V4T; ++q) {
                    float qmx = fmaxf(fmaxf(z[4*q+0], z[4*q+1]),
                                      fmaxf(z[4*q+2], z[4*q+3]));
                    int base = t + q * WORKERS;
                    if (qmx <= lo) {
                        __stcs(rout4 + base, zero);
                    } else {
#pragma unroll
                        for (int e = 0; e < 4; ++e)
                            if (z[4*q+e] <= lo) routf[4*base + e] = 0.0f;
                    }
                }
                // workers fall through to the next row immediately (no barrier)
            } else {
                // ---- solver warp: solve + scatter fixups, overlapped with the
                // workers' next-row loads; rejoins at B0(row+1)
                float tau = solve_tau(cand[p], cnt, lane);
                if (lane < cnt)
                    routf[cidx[p][lane]] = fmaxf(cand[p][lane] - tau, 0.0f);
            }
        } else {
            // ---- fallback (arbitrary data): block-wide Newton, all 9 warps;
            // solver contributes zeros. Full-store epilogue (no fixups).
            if (t == 0) s_tau = lo;
            __syncthreads();
            float tloc = s_tau;
            for (int it = 0; it < 48; ++it) {
                float s = 0.0f, k = 0.0f;
                if (isW) {
#pragma unroll
                    for (int i = 0; i < EPT; ++i) {
                        float d = z[i] - tloc;
                        if (d > 0.0f) { s += d; k += 1.0f; }
                    }
                }
#pragma unroll
                for (int off = 16; off >= 1; off >>= 1) {
                    s += __shfl_xor_sync(FULL, s, off);
                    k += __shfl_xor_sync(FULL, k, off);
                }
                if (lane == 0) { fred[wid] = s; fredb[wid] = k; }
                __syncthreads();
                if (t == 0) {
                    float S = 0.0f, K = 0.0f;
#pragma unroll
                    for (int w = 0; w < NW + 1; ++w) { S += fred[w]; K += fredb[w]; }
                    float delta = (S - 1.0f) / K;
                    s_tau  = tloc + delta;
                    s_done = (delta < 1e-7f);
                }
                __syncthreads();
                tloc = s_tau;
                if (s_done) break;
            }
            const float tau = s_tau;
            if (isW) {
                float4* rout4 = reinterpret_cast<float4*>(routf);
#pragma unroll
                for (int i = 0; i < V4T; ++i) {
                    float4 o;
                    o.x = fmaxf(z[4*i+0] - tau, 0.0f);
                    o.y = fmaxf(z[4*i+1] - tau, 0.0f);
                    o.z = fmaxf(z[4*i+2] - tau, 0.0f);
                    o.w = fmaxf(z[4*i+3] - tau, 0.0f);
                    __stcs(rout4 + t + i * WORKERS, o);
                }
            }
            __syncthreads();   // keep parity bookkeeping consistent before next row
        }
    }
}

extern "C" void kernel_launch(void* const* d_in, const int* in_sizes, int n_in,
                              void* d_out, int out_size)
{
    const float* in  = (const float*)d_in[0];
    float*       out = (float*)d_out;
    const int n_rows = in_sizes[0] / D;   // 16384
    sparsemax_kernel<<<NCTAS, THREADS>>>(in, out, n_rows);
}